// round 14
// baseline (speedup 1.0000x reference)
#include <cuda_runtime.h>

// CorrTorch 3D correlation, max_displacement=1.
// in1, in2: [1, 64, 64, 128, 128] fp32; out: [1, 27, 64, 128, 128] fp32.
//
// R13 -> R14: break the 36-accumulator register wall by splitting taps
// (dz,dy) 9-way across threadIdx.y instead of dz 3-way. Each thread owns one
// (dz,dy) row: 12 accs (3 dx-taps x 4-wide + X/Y deferred halos), loads
// 1 in1 + 1 in2 row per channel. Regs ~48 -> launch_bounds(288,4) (cap 56)
// = 36 warps/SM (56% occ); 72 in-flight LDG.128/SM = 288 wavefronts queued,
// saturating the L1 port for the first time (Little's law needs ~250).
// Port floor rises 90 -> ~134us (in1 x9 redundancy) but latency equilibrium
// (the actual 175us binder) breaks. Proven components only: R10's pinned
// load helpers, 2-stage pipeline, scalar deferred-halo FMAs.

namespace {
constexpr int C  = 64;
constexpr int DD = 64;
constexpr int HH = 128;
constexpr int WW = 128;
constexpr int HW = HH * WW;        // 16384
constexpr int CS = DD * HW;        // 1048576
constexpr int TPX = 32;            // one warp in x = one full W row
constexpr int NBLK = DD * HH * (WW / 4) / TPX;   // 8192
}

__device__ __forceinline__ float4 ldg128(const float* p) {
    float4 v;
    asm volatile("ld.global.nc.v4.f32 {%0,%1,%2,%3}, [%4];"
                 : "=f"(v.x), "=f"(v.y), "=f"(v.z), "=f"(v.w)
                 : "l"(p));
    return v;
}

__device__ __forceinline__ float4 ldg128_pred(const float* p, int pred) {
    float4 v;
    asm volatile("{\n\t"
        ".reg .pred q;\n\t"
        "setp.ne.s32 q, %5, 0;\n\t"
        "mov.f32 %0, 0f00000000;\n\t"
        "mov.f32 %1, 0f00000000;\n\t"
        "mov.f32 %2, 0f00000000;\n\t"
        "mov.f32 %3, 0f00000000;\n\t"
        "@q ld.global.nc.v4.f32 {%0,%1,%2,%3}, [%4];\n\t"
        "}"
        : "=f"(v.x), "=f"(v.y), "=f"(v.z), "=f"(v.w)
        : "l"(p), "r"(pred));
    return v;
}

struct Acc {
    float d0[3];   // dx=0: out1..out3
    float d1[4];   // dx=1: out0..out3
    float d2[3];   // dx=2: out0..out2
    float X;       // dx=0: halo sum -> right neighbor's out0
    float Y;       // dx=2: halo sum -> left neighbor's out3
};

__device__ __forceinline__ void do_compute(const float4& a, const float4& r,
                                           float an0, float ap3, Acc& A)
{
    // dx = 1: out[j] = a[j] * r[j]
    A.d1[0] = fmaf(a.x, r.x, A.d1[0]);
    A.d1[1] = fmaf(a.y, r.y, A.d1[1]);
    A.d1[2] = fmaf(a.z, r.z, A.d1[2]);
    A.d1[3] = fmaf(a.w, r.w, A.d1[3]);
    // dx = 0: out[j] = a[j] * r[j-1], j=1..3; halo (j=0) deferred via X
    A.d0[0] = fmaf(a.y, r.x, A.d0[0]);
    A.d0[1] = fmaf(a.z, r.y, A.d0[1]);
    A.d0[2] = fmaf(a.w, r.z, A.d0[2]);
    A.X     = fmaf(an0, r.w, A.X);
    // dx = 2: out[j] = a[j] * r[j+1], j=0..2; halo (j=3) deferred via Y
    A.d2[0] = fmaf(a.x, r.y, A.d2[0]);
    A.d2[1] = fmaf(a.y, r.z, A.d2[1]);
    A.d2[2] = fmaf(a.z, r.w, A.d2[2]);
    A.Y     = fmaf(ap3, r.x, A.Y);
}

__global__ void __launch_bounds__(TPX * 9, 4) corr3d_kernel(
    const float* __restrict__ in1,
    const float* __restrict__ in2,
    float* __restrict__ out)
{
    const int s  = blockIdx.x * TPX + threadIdx.x;  // strip id
    const int g  = threadIdx.y;                     // 0..8 tap group
    const int dz = g / 3;
    const int dy = g % 3;
    const int lane = threadIdx.x & 31;
    const int w0 = (s & 31) << 2;                   // 0,4,...,124
    const int h  = (s >> 5) & 127;
    const int d  = s >> 12;

    const int zp  = d + dz - 1;                     // in2 source plane
    const int row = h + dy - 1;                     // in2 source row
    const int pred = (zp >= 0) && (zp < DD) && (row >= 0) && (row < HH);
    const bool pw0 = (lane > 0);
    const bool pw5 = (lane < 31);

    const float* q1 = in1 + d * HW + h * WW + w0;
    const float* q2 = in2 + zp * HW + row * WW + w0;

    Acc A;
    A.d0[0] = A.d0[1] = A.d0[2] = 0.f;
    A.d1[0] = A.d1[1] = A.d1[2] = A.d1[3] = 0.f;
    A.d2[0] = A.d2[1] = A.d2[2] = 0.f;
    A.X = 0.f; A.Y = 0.f;

    float4 aA, aB, rA, rB;

    aA = ldg128(q1);
    rA = ldg128_pred(q2, pred);                     // c = 0

#pragma unroll 2
    for (int c = 0; c < C - 2; c += 2) {
        q1 += CS; q2 += CS;
        aB = ldg128(q1);                            // c+1 in flight
        rB = ldg128_pred(q2, pred);
        {
            float an0 = __shfl_down_sync(0xffffffffu, aA.x, 1);
            float ap3 = __shfl_up_sync  (0xffffffffu, aA.w, 1);
            do_compute(aA, rA, an0, ap3, A);        // consume c
        }
        q1 += CS; q2 += CS;
        aA = ldg128(q1);                            // c+2 in flight
        rA = ldg128_pred(q2, pred);
        {
            float an0 = __shfl_down_sync(0xffffffffu, aB.x, 1);
            float ap3 = __shfl_up_sync  (0xffffffffu, aB.w, 1);
            do_compute(aB, rB, an0, ap3, A);        // consume c+1
        }
    }
    q1 += CS; q2 += CS;
    aB = ldg128(q1);                                // c = C-1
    rB = ldg128_pred(q2, pred);
    {
        float an0 = __shfl_down_sync(0xffffffffu, aA.x, 1);
        float ap3 = __shfl_up_sync  (0xffffffffu, aA.w, 1);
        do_compute(aA, rA, an0, ap3, A);
    }
    {
        float an0 = __shfl_down_sync(0xffffffffu, aB.x, 1);
        float ap3 = __shfl_up_sync  (0xffffffffu, aB.w, 1);
        do_compute(aB, rB, an0, ap3, A);
    }

    float* op = out + (long)(g * 3) * CS + d * HW + h * WW + w0;
    const float inv = 1.0f / 64.0f;

    // dx = 0: out0 comes from the left neighbor's X
    float xin = __shfl_up_sync(0xffffffffu, A.X, 1);
    float4 v0 = make_float4(pw0 ? xin * inv : 0.f,
                            A.d0[0] * inv, A.d0[1] * inv, A.d0[2] * inv);
    *reinterpret_cast<float4*>(op + 0L * CS) = v0;
    // dx = 1
    float4 v1 = make_float4(A.d1[0] * inv, A.d1[1] * inv,
                            A.d1[2] * inv, A.d1[3] * inv);
    *reinterpret_cast<float4*>(op + 1L * CS) = v1;
    // dx = 2: out3 comes from the right neighbor's Y
    float yin = __shfl_down_sync(0xffffffffu, A.Y, 1);
    float4 v2 = make_float4(A.d2[0] * inv, A.d2[1] * inv, A.d2[2] * inv,
                            pw5 ? yin * inv : 0.f);
    *reinterpret_cast<float4*>(op + 2L * CS) = v2;
}

extern "C" void kernel_launch(void* const* d_in, const int* in_sizes, int n_in,
                              void* d_out, int out_size)
{
    const float* in1 = (const float*)d_in[0];
    const float* in2 = (const float*)d_in[1];
    float* out = (float*)d_out;
    (void)in_sizes; (void)n_in; (void)out_size;

    dim3 blk(TPX, 9);
    corr3d_kernel<<<NBLK, blk>>>(in1, in2, out);
}

// round 15
// speedup vs baseline: 1.7057x; 1.7057x over previous
#include <cuda_runtime.h>

// CorrTorch 3D correlation, max_displacement=1.
// in1, in2: [1, 64, 64, 128, 128] fp32; out: [1, 27, 64, 128, 128] fp32.
//
// R14 -> R15: register-free pipeline deepening on the champion (R10).
// Every register-funded MLP attempt (R6/R11 stage rings) and every occupancy
// trade (R7/R12/R14) failed; the ~600 exposed stall cycles per warp-channel
// remained. prefetch.global.L1 adds load-ahead WITHOUT registers or
// scoreboard: channels c+3/c+4 are prefetched ~2 bodies (~450 contended cyc)
// before their pinned LDG.128s issue, converting those loads into L1 hits
// (~39 cyc). Prefetch footprint ~98KB < 228KB L1. c+3 is always in-range;
// c+4 guarded by (c+4<C); in2 rows guarded by the loop-invariant rv preds.
// Everything else is bit-identical to R10 (2-stage pipeline, (64,3)x192
// blocks, launch_bounds(192,4), scalar deferred-halo FMAs, pinned loads).

namespace {
constexpr int C  = 64;
constexpr int DD = 64;
constexpr int HH = 128;
constexpr int WW = 128;
constexpr int HW = HH * WW;        // 16384
constexpr int CS = DD * HW;        // 1048576
constexpr int TPX = 64;            // 2 warps in x, each = one full W row
constexpr int NBLK = DD * HH * (WW / 4) / TPX;   // 4096
}

__device__ __forceinline__ float4 ldg128(const float* p) {
    float4 v;
    asm volatile("ld.global.nc.v4.f32 {%0,%1,%2,%3}, [%4];"
                 : "=f"(v.x), "=f"(v.y), "=f"(v.z), "=f"(v.w)
                 : "l"(p));
    return v;
}

__device__ __forceinline__ float4 ldg128_pred(const float* p, int pred) {
    float4 v;
    asm volatile("{\n\t"
        ".reg .pred q;\n\t"
        "setp.ne.s32 q, %5, 0;\n\t"
        "mov.f32 %0, 0f00000000;\n\t"
        "mov.f32 %1, 0f00000000;\n\t"
        "mov.f32 %2, 0f00000000;\n\t"
        "mov.f32 %3, 0f00000000;\n\t"
        "@q ld.global.nc.v4.f32 {%0,%1,%2,%3}, [%4];\n\t"
        "}"
        : "=f"(v.x), "=f"(v.y), "=f"(v.z), "=f"(v.w)
        : "l"(p), "r"(pred));
    return v;
}

__device__ __forceinline__ void pf_l1(const float* p) {
    asm volatile("prefetch.global.L1 [%0];" :: "l"(p));
}
__device__ __forceinline__ void pf_l1_pred(const float* p, int pred) {
    asm volatile("{\n\t"
        ".reg .pred q;\n\t"
        "setp.ne.s32 q, %1, 0;\n\t"
        "@q prefetch.global.L1 [%0];\n\t"
        "}"
        :: "l"(p), "r"(pred));
}

struct Acc {
    float d0[3][3];   // dx=0: out1..out3 per dy
    float X[3];       // dx=0: halo sum -> right neighbor's out0
    float d1[3][4];   // dx=1: out0..out3
    float d2[3][3];   // dx=2: out0..out2
    float Y[3];       // dx=2: halo sum -> left neighbor's out3
};

__device__ __forceinline__ void ld_stage(const float* __restrict__ q1,
                                         const float* __restrict__ q2,
                                         const int rv[3],
                                         float4& a, float4 rm[3])
{
    a = ldg128(q1);
#pragma unroll
    for (int dy = 0; dy < 3; dy++) {
        rm[dy] = ldg128_pred(q2 + dy * WW, rv[dy]);
    }
}

__device__ __forceinline__ void do_compute(const float4& a, const float4 rm[3],
                                           Acc& A)
{
    float an0 = __shfl_down_sync(0xffffffffu, a.x, 1);  // right lane's a0
    float ap3 = __shfl_up_sync  (0xffffffffu, a.w, 1);  // left lane's a3
#pragma unroll
    for (int dy = 0; dy < 3; dy++) {
        const float4 r = rm[dy];
        // dx = 1: out[j] = a[j] * r[j]
        A.d1[dy][0] = fmaf(a.x, r.x, A.d1[dy][0]);
        A.d1[dy][1] = fmaf(a.y, r.y, A.d1[dy][1]);
        A.d1[dy][2] = fmaf(a.z, r.z, A.d1[dy][2]);
        A.d1[dy][3] = fmaf(a.w, r.w, A.d1[dy][3]);
        // dx = 0: out[j] = a[j] * r[j-1], j=1..3; halo (j=0) deferred via X
        A.d0[dy][0] = fmaf(a.y, r.x, A.d0[dy][0]);
        A.d0[dy][1] = fmaf(a.z, r.y, A.d0[dy][1]);
        A.d0[dy][2] = fmaf(a.w, r.z, A.d0[dy][2]);
        A.X[dy]     = fmaf(an0, r.w, A.X[dy]);
        // dx = 2: out[j] = a[j] * r[j+1], j=0..2; halo (j=3) deferred via Y
        A.d2[dy][0] = fmaf(a.x, r.y, A.d2[dy][0]);
        A.d2[dy][1] = fmaf(a.y, r.z, A.d2[dy][1]);
        A.d2[dy][2] = fmaf(a.z, r.w, A.d2[dy][2]);
        A.Y[dy]     = fmaf(ap3, r.x, A.Y[dy]);
    }
}

__global__ void __launch_bounds__(TPX * 3, 4) corr3d_kernel(
    const float* __restrict__ in1,
    const float* __restrict__ in2,
    float* __restrict__ out)
{
    const int s  = blockIdx.x * TPX + threadIdx.x;  // strip id
    const int dz = threadIdx.y;                     // 0..2
    const int lane = threadIdx.x & 31;
    const int w0 = (s & 31) << 2;                   // 0,4,...,124
    const int h  = (s >> 5) & 127;
    const int d  = s >> 12;

    const int zp = d + dz - 1;                      // in2 source plane
    const int pz = (zp >= 0) && (zp < DD);
    const int rv[3] = { pz && (h > 0), pz, pz && (h < HH - 1) };
    const bool pw0 = (lane > 0);
    const bool pw5 = (lane < 31);

    const float* q1 = in1 + d * HW + h * WW + w0;
    const float* q2 = in2 + zp * HW + (h - 1) * WW + w0;

    Acc A;
#pragma unroll
    for (int dy = 0; dy < 3; dy++) {
        A.d0[dy][0] = A.d0[dy][1] = A.d0[dy][2] = 0.f;
        A.d1[dy][0] = A.d1[dy][1] = A.d1[dy][2] = A.d1[dy][3] = 0.f;
        A.d2[dy][0] = A.d2[dy][1] = A.d2[dy][2] = 0.f;
        A.X[dy] = 0.f; A.Y[dy] = 0.f;
    }

    float4 aA, aB;
    float4 rmA[3], rmB[3];

    ld_stage(q1, q2, rv, aA, rmA);                  // c = 0

#pragma unroll 2
    for (int c = 0; c < C - 2; c += 2) {
        q1 += CS; q2 += CS;
        ld_stage(q1, q2, rv, aB, rmB);              // c+1 in flight
        // prefetch channel c+3 into L1 (always in range: c+3 <= 63)
        pf_l1(q1 + 2 * CS);
        pf_l1_pred(q2 + 2 * CS,          rv[0]);
        pf_l1_pred(q2 + 2 * CS + WW,     rv[1]);
        pf_l1_pred(q2 + 2 * CS + 2 * WW, rv[2]);
        do_compute(aA, rmA, A);                     // consume c
        q1 += CS; q2 += CS;
        ld_stage(q1, q2, rv, aA, rmA);              // c+2 in flight
        // prefetch channel c+4 into L1 (guarded: last iter would be OOB)
        {
            int ok = (c + 4) < C;
            pf_l1_pred(q1 + 2 * CS,          ok);
            pf_l1_pred(q2 + 2 * CS,          rv[0] & ok);
            pf_l1_pred(q2 + 2 * CS + WW,     rv[1] & ok);
            pf_l1_pred(q2 + 2 * CS + 2 * WW, rv[2] & ok);
        }
        do_compute(aB, rmB, A);                     // consume c+1
    }
    q1 += CS; q2 += CS;
    ld_stage(q1, q2, rv, aB, rmB);                  // c = C-1
    do_compute(aA, rmA, A);
    do_compute(aB, rmB, A);

    float* op = out + (long)(dz * 9) * CS + d * HW + h * WW + w0;
    const float inv = 1.0f / 64.0f;
#pragma unroll
    for (int dy = 0; dy < 3; dy++) {
        // dx = 0: out0 comes from the left neighbor's X
        float xin = __shfl_up_sync(0xffffffffu, A.X[dy], 1);
        float4 v0 = make_float4(pw0 ? xin * inv : 0.f,
                                A.d0[dy][0] * inv, A.d0[dy][1] * inv,
                                A.d0[dy][2] * inv);
        *reinterpret_cast<float4*>(op + (long)(dy * 3 + 0) * CS) = v0;
        // dx = 1
        float4 v1 = make_float4(A.d1[dy][0] * inv, A.d1[dy][1] * inv,
                                A.d1[dy][2] * inv, A.d1[dy][3] * inv);
        *reinterpret_cast<float4*>(op + (long)(dy * 3 + 1) * CS) = v1;
        // dx = 2: out3 comes from the right neighbor's Y
        float yin = __shfl_down_sync(0xffffffffu, A.Y[dy], 1);
        float4 v2 = make_float4(A.d2[dy][0] * inv, A.d2[dy][1] * inv,
                                A.d2[dy][2] * inv,
                                pw5 ? yin * inv : 0.f);
        *reinterpret_cast<float4*>(op + (long)(dy * 3 + 2) * CS) = v2;
    }
}

extern "C" void kernel_launch(void* const* d_in, const int* in_sizes, int n_in,
                              void* d_out, int out_size)
{
    const float* in1 = (const float*)d_in[0];
    const float* in2 = (const float*)d_in[1];
    float* out = (float*)d_out;
    (void)in_sizes; (void)n_in; (void)out_size;

    dim3 blk(TPX, 3);
    corr3d_kernel<<<NBLK, blk>>>(in1, in2, out);
}

// round 16
// speedup vs baseline: 1.7385x; 1.0193x over previous
#include <cuda_runtime.h>

// CorrTorch 3D correlation, max_displacement=1.
// in1, in2: [1, 64, 64, 128, 128] fp32; out: [1, 27, 64, 128, 128] fp32.
//
// R15 -> R16: single-variable fix of the prefetch path mismatch. R15 showed
// L2=99% (2.5x traffic) with no latency win: ld.global.NC routes via the
// texture path, but prefetch.global.L1 fills the generic L1 path -> the
// prefetched lines were invisible to the loads, so every line crossed L2
// twice. This round drops .nc so loads and prefetches share the same L1:
// the pinned LDG.128s should now hit prefetched lines (~39cyc vs ~250+).
// Everything else is bit-identical to R15 (2-stage pipeline, (64,3)x192
// blocks, launch_bounds(192,4), scalar deferred-halo FMAs, c+3/c+4
// prefetch).

namespace {
constexpr int C  = 64;
constexpr int DD = 64;
constexpr int HH = 128;
constexpr int WW = 128;
constexpr int HW = HH * WW;        // 16384
constexpr int CS = DD * HW;        // 1048576
constexpr int TPX = 64;            // 2 warps in x, each = one full W row
constexpr int NBLK = DD * HH * (WW / 4) / TPX;   // 4096
}

__device__ __forceinline__ float4 ldg128(const float* p) {
    float4 v;
    asm volatile("ld.global.v4.f32 {%0,%1,%2,%3}, [%4];"
                 : "=f"(v.x), "=f"(v.y), "=f"(v.z), "=f"(v.w)
                 : "l"(p));
    return v;
}

__device__ __forceinline__ float4 ldg128_pred(const float* p, int pred) {
    float4 v;
    asm volatile("{\n\t"
        ".reg .pred q;\n\t"
        "setp.ne.s32 q, %5, 0;\n\t"
        "mov.f32 %0, 0f00000000;\n\t"
        "mov.f32 %1, 0f00000000;\n\t"
        "mov.f32 %2, 0f00000000;\n\t"
        "mov.f32 %3, 0f00000000;\n\t"
        "@q ld.global.v4.f32 {%0,%1,%2,%3}, [%4];\n\t"
        "}"
        : "=f"(v.x), "=f"(v.y), "=f"(v.z), "=f"(v.w)
        : "l"(p), "r"(pred));
    return v;
}

__device__ __forceinline__ void pf_l1(const float* p) {
    asm volatile("prefetch.global.L1 [%0];" :: "l"(p));
}
__device__ __forceinline__ void pf_l1_pred(const float* p, int pred) {
    asm volatile("{\n\t"
        ".reg .pred q;\n\t"
        "setp.ne.s32 q, %1, 0;\n\t"
        "@q prefetch.global.L1 [%0];\n\t"
        "}"
        :: "l"(p), "r"(pred));
}

struct Acc {
    float d0[3][3];   // dx=0: out1..out3 per dy
    float X[3];       // dx=0: halo sum -> right neighbor's out0
    float d1[3][4];   // dx=1: out0..out3
    float d2[3][3];   // dx=2: out0..out2
    float Y[3];       // dx=2: halo sum -> left neighbor's out3
};

__device__ __forceinline__ void ld_stage(const float* __restrict__ q1,
                                         const float* __restrict__ q2,
                                         const int rv[3],
                                         float4& a, float4 rm[3])
{
    a = ldg128(q1);
#pragma unroll
    for (int dy = 0; dy < 3; dy++) {
        rm[dy] = ldg128_pred(q2 + dy * WW, rv[dy]);
    }
}

__device__ __forceinline__ void do_compute(const float4& a, const float4 rm[3],
                                           Acc& A)
{
    float an0 = __shfl_down_sync(0xffffffffu, a.x, 1);  // right lane's a0
    float ap3 = __shfl_up_sync  (0xffffffffu, a.w, 1);  // left lane's a3
#pragma unroll
    for (int dy = 0; dy < 3; dy++) {
        const float4 r = rm[dy];
        // dx = 1: out[j] = a[j] * r[j]
        A.d1[dy][0] = fmaf(a.x, r.x, A.d1[dy][0]);
        A.d1[dy][1] = fmaf(a.y, r.y, A.d1[dy][1]);
        A.d1[dy][2] = fmaf(a.z, r.z, A.d1[dy][2]);
        A.d1[dy][3] = fmaf(a.w, r.w, A.d1[dy][3]);
        // dx = 0: out[j] = a[j] * r[j-1], j=1..3; halo (j=0) deferred via X
        A.d0[dy][0] = fmaf(a.y, r.x, A.d0[dy][0]);
        A.d0[dy][1] = fmaf(a.z, r.y, A.d0[dy][1]);
        A.d0[dy][2] = fmaf(a.w, r.z, A.d0[dy][2]);
        A.X[dy]     = fmaf(an0, r.w, A.X[dy]);
        // dx = 2: out[j] = a[j] * r[j+1], j=0..2; halo (j=3) deferred via Y
        A.d2[dy][0] = fmaf(a.x, r.y, A.d2[dy][0]);
        A.d2[dy][1] = fmaf(a.y, r.z, A.d2[dy][1]);
        A.d2[dy][2] = fmaf(a.z, r.w, A.d2[dy][2]);
        A.Y[dy]     = fmaf(ap3, r.x, A.Y[dy]);
    }
}

__global__ void __launch_bounds__(TPX * 3, 4) corr3d_kernel(
    const float* __restrict__ in1,
    const float* __restrict__ in2,
    float* __restrict__ out)
{
    const int s  = blockIdx.x * TPX + threadIdx.x;  // strip id
    const int dz = threadIdx.y;                     // 0..2
    const int lane = threadIdx.x & 31;
    const int w0 = (s & 31) << 2;                   // 0,4,...,124
    const int h  = (s >> 5) & 127;
    const int d  = s >> 12;

    const int zp = d + dz - 1;                      // in2 source plane
    const int pz = (zp >= 0) && (zp < DD);
    const int rv[3] = { pz && (h > 0), pz, pz && (h < HH - 1) };
    const bool pw0 = (lane > 0);
    const bool pw5 = (lane < 31);

    const float* q1 = in1 + d * HW + h * WW + w0;
    const float* q2 = in2 + zp * HW + (h - 1) * WW + w0;

    Acc A;
#pragma unroll
    for (int dy = 0; dy < 3; dy++) {
        A.d0[dy][0] = A.d0[dy][1] = A.d0[dy][2] = 0.f;
        A.d1[dy][0] = A.d1[dy][1] = A.d1[dy][2] = A.d1[dy][3] = 0.f;
        A.d2[dy][0] = A.d2[dy][1] = A.d2[dy][2] = 0.f;
        A.X[dy] = 0.f; A.Y[dy] = 0.f;
    }

    float4 aA, aB;
    float4 rmA[3], rmB[3];

    ld_stage(q1, q2, rv, aA, rmA);                  // c = 0

#pragma unroll 2
    for (int c = 0; c < C - 2; c += 2) {
        q1 += CS; q2 += CS;
        ld_stage(q1, q2, rv, aB, rmB);              // c+1 in flight
        // prefetch channel c+3 into L1 (always in range: c+3 <= 63)
        pf_l1(q1 + 2 * CS);
        pf_l1_pred(q2 + 2 * CS,          rv[0]);
        pf_l1_pred(q2 + 2 * CS + WW,     rv[1]);
        pf_l1_pred(q2 + 2 * CS + 2 * WW, rv[2]);
        do_compute(aA, rmA, A);                     // consume c
        q1 += CS; q2 += CS;
        ld_stage(q1, q2, rv, aA, rmA);              // c+2 in flight
        // prefetch channel c+4 into L1 (guarded: last iter would be OOB)
        {
            int ok = (c + 4) < C;
            pf_l1_pred(q1 + 2 * CS,          ok);
            pf_l1_pred(q2 + 2 * CS,          rv[0] & ok);
            pf_l1_pred(q2 + 2 * CS + WW,     rv[1] & ok);
            pf_l1_pred(q2 + 2 * CS + 2 * WW, rv[2] & ok);
        }
        do_compute(aB, rmB, A);                     // consume c+1
    }
    q1 += CS; q2 += CS;
    ld_stage(q1, q2, rv, aB, rmB);                  // c = C-1
    do_compute(aA, rmA, A);
    do_compute(aB, rmB, A);

    float* op = out + (long)(dz * 9) * CS + d * HW + h * WW + w0;
    const float inv = 1.0f / 64.0f;
#pragma unroll
    for (int dy = 0; dy < 3; dy++) {
        // dx = 0: out0 comes from the left neighbor's X
        float xin = __shfl_up_sync(0xffffffffu, A.X[dy], 1);
        float4 v0 = make_float4(pw0 ? xin * inv : 0.f,
                                A.d0[dy][0] * inv, A.d0[dy][1] * inv,
                                A.d0[dy][2] * inv);
        *reinterpret_cast<float4*>(op + (long)(dy * 3 + 0) * CS) = v0;
        // dx = 1
        float4 v1 = make_float4(A.d1[dy][0] * inv, A.d1[dy][1] * inv,
                                A.d1[dy][2] * inv, A.d1[dy][3] * inv);
        *reinterpret_cast<float4*>(op + (long)(dy * 3 + 1) * CS) = v1;
        // dx = 2: out3 comes from the right neighbor's Y
        float yin = __shfl_down_sync(0xffffffffu, A.Y[dy], 1);
        float4 v2 = make_float4(A.d2[dy][0] * inv, A.d2[dy][1] * inv,
                                A.d2[dy][2] * inv,
                                pw5 ? yin * inv : 0.f);
        *reinterpret_cast<float4*>(op + (long)(dy * 3 + 2) * CS) = v2;
    }
}

extern "C" void kernel_launch(void* const* d_in, const int* in_sizes, int n_in,
                              void* d_out, int out_size)
{
    const float* in1 = (const float*)d_in[0];
    const float* in2 = (const float*)d_in[1];
    float* out = (float*)d_out;
    (void)in_sizes; (void)n_in; (void)out_size;

    dim3 blk(TPX, 3);
    corr3d_kernel<<<NBLK, blk>>>(in1, in2, out);
}